// round 2
// baseline (speedup 1.0000x reference)
#include <cuda_runtime.h>
#include <math.h>

// Problem constants
#define BB 2
#define LL 1024
#define DM 1024
#define DI 2048
#define DS 16
#define DR 64
#define NX 96          // DR + 2*DS
#define MROWS 2048     // B*L

// ---------------- scratch (device globals; no allocation allowed) -----------
__device__ float g_xz[(size_t)MROWS * 2 * DI];     // 2048 x 4096
__device__ float g_xc[(size_t)MROWS * DI];         // 2048 x 2048 (conv+silu output)
__device__ float g_xdbl[(size_t)MROWS * NX];       // 2048 x 96
__device__ float g_part[(size_t)8 * MROWS * NX];   // split-K partials for GEMM2
__device__ float g_delta[(size_t)MROWS * DI];      // 2048 x 2048
__device__ float g_y[(size_t)MROWS * DI];          // 2048 x 2048

// ---------------- packed f32x2 helpers (full-rate fp32 on sm_103a) ----------
__device__ __forceinline__ unsigned long long pk2(float lo, float hi) {
    unsigned long long r;
    asm("mov.b64 %0, {%1,%2};" : "=l"(r) : "f"(lo), "f"(hi));
    return r;
}
__device__ __forceinline__ void fma2(unsigned long long& d, unsigned long long a,
                                     unsigned long long b) {
    asm("fma.rn.f32x2 %0, %1, %2, %0;" : "+l"(d) : "l"(a), "l"(b));
}
__device__ __forceinline__ void upk2(unsigned long long v, float& lo, float& hi) {
    asm("mov.b64 {%0,%1}, %2;" : "=f"(lo), "=f"(hi) : "l"(v));
}

__device__ __forceinline__ float softplus_f(float v) {
    return fmaxf(v, 0.f) + log1pf(__expf(-fabsf(v)));
}

// ---------------- SGEMM: C[M,N] = A[M,K(lda)] @ B[K,N], fp32, f32x2 core ----
// BM=128, BN=128, BK=8, 256 threads, 8x8 per-thread microtile.
// gridDim.z > 1 => split-K: block z computes K-chunk z, writes to C + z*M*N.
// EPI: 0 = plain store, 1 = softplus(acc + bias[col])
#define BM 128
#define BN 128
#define BK 8

__device__ __forceinline__ float4 ldB_guard(const float* __restrict__ B, int k,
                                            int gc, int N) {
    if (gc + 3 < N) return *(const float4*)(B + (size_t)k * N + gc);
    float4 r = {0.f, 0.f, 0.f, 0.f};
    if (gc + 0 < N) r.x = B[(size_t)k * N + gc + 0];
    if (gc + 1 < N) r.y = B[(size_t)k * N + gc + 1];
    if (gc + 2 < N) r.z = B[(size_t)k * N + gc + 2];
    if (gc + 3 < N) r.w = B[(size_t)k * N + gc + 3];
    return r;
}

template <int EPI>
__global__ __launch_bounds__(256, 2) void sgemm_kernel(
    const float* __restrict__ A, const float* __restrict__ B,
    float* __restrict__ C, int M, int N, int K, int lda,
    const float* __restrict__ bias) {
    __shared__ __align__(16) float As[BK][BM];
    __shared__ __align__(16) float Bs[BK][BN];

    const int tid = threadIdx.x;
    const int brow = blockIdx.y * BM;
    const int bcol = blockIdx.x * BN;

    // split-K chunk
    const int kc = K / gridDim.z;
    const int kbeg = blockIdx.z * kc;
    const int kend = kbeg + kc;
    float* __restrict__ Cb = C + (size_t)blockIdx.z * (size_t)M * (size_t)N;

    const int arow = tid >> 1;          // 0..127
    const int acol = (tid & 1) * 4;     // 0 or 4
    const int bkrow = tid >> 5;         // 0..7
    const int bncol = (tid & 31) * 4;   // 0..124

    const int trow = (tid >> 4) * 8;
    const int tcol = (tid & 15) * 8;

    unsigned long long acc[8][4];
#pragma unroll
    for (int i = 0; i < 8; ++i)
#pragma unroll
        for (int j = 0; j < 4; ++j) acc[i][j] = 0ull;

    const float* Aptr = A + (size_t)(brow + arow) * lda + acol;

    // prologue load
    float4 a4 = *(const float4*)(Aptr + kbeg);
    float4 b4 = ldB_guard(B, kbeg + bkrow, bcol + bncol, N);

    for (int k0 = kbeg;;) {
        As[acol + 0][arow] = a4.x;
        As[acol + 1][arow] = a4.y;
        As[acol + 2][arow] = a4.z;
        As[acol + 3][arow] = a4.w;
        *(float4*)&Bs[bkrow][bncol] = b4;
        __syncthreads();

        const int knext = k0 + BK;
        if (knext < kend) {
            a4 = *(const float4*)(Aptr + knext);
            b4 = ldB_guard(B, knext + bkrow, bcol + bncol, N);
        }

#pragma unroll
        for (int kk = 0; kk < BK; ++kk) {
            float4 a0 = *(const float4*)&As[kk][trow];
            float4 a1 = *(const float4*)&As[kk][trow + 4];
            float4 b0 = *(const float4*)&Bs[kk][tcol];
            float4 b1 = *(const float4*)&Bs[kk][tcol + 4];
            unsigned long long bp0 = pk2(b0.x, b0.y);
            unsigned long long bp1 = pk2(b0.z, b0.w);
            unsigned long long bp2 = pk2(b1.x, b1.y);
            unsigned long long bp3 = pk2(b1.z, b1.w);
            float av[8] = {a0.x, a0.y, a0.z, a0.w, a1.x, a1.y, a1.z, a1.w};
#pragma unroll
            for (int i = 0; i < 8; ++i) {
                unsigned long long ap = pk2(av[i], av[i]);
                fma2(acc[i][0], ap, bp0);
                fma2(acc[i][1], ap, bp1);
                fma2(acc[i][2], ap, bp2);
                fma2(acc[i][3], ap, bp3);
            }
        }
        k0 = knext;
        if (k0 >= kend) break;
        __syncthreads();
    }

    // epilogue (M is always a multiple of BM here; guard N only)
    const int row0 = brow + trow;
    const int col0 = bcol + tcol;
#pragma unroll
    for (int i = 0; i < 8; ++i) {
        const size_t rbase = (size_t)(row0 + i) * N;
#pragma unroll
        for (int j = 0; j < 4; ++j) {
            float lo, hi;
            upk2(acc[i][j], lo, hi);
            const int cc = col0 + 2 * j;
            if (EPI == 1) {
                if (cc < N) Cb[rbase + cc] = softplus_f(lo + bias[cc]);
                if (cc + 1 < N) Cb[rbase + cc + 1] = softplus_f(hi + bias[cc + 1]);
            } else {
                if (cc < N) Cb[rbase + cc] = lo;
                if (cc + 1 < N) Cb[rbase + cc + 1] = hi;
            }
        }
    }
}

// ---------------- causal depthwise conv (k=4) + SiLU ------------------------
// x = g_xz[:, 0:DI]; output g_xc (MROWS x DI). One thread per 4 channels.
__global__ __launch_bounds__(256) void conv_silu_kernel(
    const float* __restrict__ xz, const float* __restrict__ kern,
    const float* __restrict__ kb, float* __restrict__ xc) {
    const int idx = blockIdx.x * blockDim.x + threadIdx.x;  // 0 .. MROWS*DI/4
    const int d4 = idx & (DI / 4 - 1);
    const int row = idx / (DI / 4);
    const int l = row & (LL - 1);
    const int d = d4 * 4;

    float4 acc = *(const float4*)(kb + d);
#pragma unroll
    for (int i = 0; i < 4; ++i) {
        const int ll = l - 3 + i;
        if (ll >= 0) {
            const float4 x4 = *(const float4*)(xz + (size_t)(row - 3 + i) * (2 * DI) + d);
            const float4 k4 = *(const float4*)(kern + i * DI + d);
            acc.x = fmaf(x4.x, k4.x, acc.x);
            acc.y = fmaf(x4.y, k4.y, acc.y);
            acc.z = fmaf(x4.z, k4.z, acc.z);
            acc.w = fmaf(x4.w, k4.w, acc.w);
        }
    }
    acc.x = acc.x / (1.f + __expf(-acc.x));
    acc.y = acc.y / (1.f + __expf(-acc.y));
    acc.z = acc.z / (1.f + __expf(-acc.z));
    acc.w = acc.w / (1.f + __expf(-acc.w));
    *(float4*)(xc + (size_t)row * DI + d) = acc;
}

// ---------------- split-K reduce for GEMM2 (deterministic) ------------------
__global__ __launch_bounds__(256) void reduce8_kernel(const float* __restrict__ part,
                                                      float* __restrict__ out) {
    const int i = blockIdx.x * blockDim.x + threadIdx.x;
    if (i < MROWS * NX) {
        float s = 0.f;
#pragma unroll
        for (int c = 0; c < 8; ++c) s += part[(size_t)c * (MROWS * NX) + i];
        out[i] = s;
    }
}

// ---------------- selective scan --------------------------------------------
// warp = 2 d-channels x 16 states. 2048 warps total (256 blocks x 8 warps).
__global__ __launch_bounds__(256) void scan_kernel(
    const float* __restrict__ xc, const float* __restrict__ xdbl,
    const float* __restrict__ delta, const float* __restrict__ xz,
    const float* __restrict__ A_log, const float* __restrict__ Dskip,
    float* __restrict__ y) {
    const int w = blockIdx.x * 8 + (threadIdx.x >> 5);
    const int lane = threadIdx.x & 31;
    const int b = w >> 10;          // batch
    const int dp = w & 1023;        // d-pair index
    const int n = lane & 15;        // state index
    const int d = dp * 2 + (lane >> 4);

    const float An = -expf(A_log[d * DS + n]);
    const float Dv = Dskip[d];

    const size_t rb = (size_t)(b << 10);
    const float* __restrict__ dptr = delta + rb * DI + d;
    const float* __restrict__ uptr = xc + rb * DI + d;
    const float* __restrict__ zptr = xz + rb * (2 * DI) + DI + d;
    const float* __restrict__ bcb = xdbl + rb * NX;
    float* __restrict__ yptr = y + rb * DI + d;

    float st = 0.f;
#pragma unroll 2
    for (int l = 0; l < LL; ++l) {
        const float dl = __ldg(dptr + (size_t)l * DI);
        const float u = __ldg(uptr + (size_t)l * DI);
        const float Bn = __ldg(bcb + (size_t)l * NX + DR + n);
        const float Cn = __ldg(bcb + (size_t)l * NX + DR + DS + n);
        const float dA = __expf(dl * An);
        st = fmaf(dA, st, dl * u * Bn);
        float c = st * Cn;
        c += __shfl_xor_sync(0xffffffffu, c, 8);
        c += __shfl_xor_sync(0xffffffffu, c, 4);
        c += __shfl_xor_sync(0xffffffffu, c, 2);
        c += __shfl_xor_sync(0xffffffffu, c, 1);
        if (n == 0) {
            const float zv = __ldg(zptr + (size_t)l * (2 * DI));
            const float yv = fmaf(u, Dv, c);
            yptr[(size_t)l * DI] = yv * zv / (1.f + __expf(-zv));
        }
    }
}

// ---------------- launch ----------------------------------------------------
extern "C" void kernel_launch(void* const* d_in, const int* in_sizes, int n_in,
                              void* d_out, int out_size) {
    (void)in_sizes; (void)n_in; (void)out_size;
    const float* hidden = (const float*)d_in[0];
    const float* Win = (const float*)d_in[1];
    const float* Wx = (const float*)d_in[2];
    const float* Wdt = (const float*)d_in[3];
    const float* dt_bias = (const float*)d_in[4];
    const float* Wout = (const float*)d_in[5];
    const float* dwk = (const float*)d_in[6];
    const float* dwb = (const float*)d_in[7];
    const float* A_log = (const float*)d_in[8];
    const float* Dskip = (const float*)d_in[9];
    float* out = (float*)d_out;

    float *xz, *xc, *xdbl, *part, *dlt, *yb;
    cudaGetSymbolAddress((void**)&xz, g_xz);
    cudaGetSymbolAddress((void**)&xc, g_xc);
    cudaGetSymbolAddress((void**)&xdbl, g_xdbl);
    cudaGetSymbolAddress((void**)&part, g_part);
    cudaGetSymbolAddress((void**)&dlt, g_delta);
    cudaGetSymbolAddress((void**)&yb, g_y);

    const dim3 thr(256);

    // 1) xz = hidden @ Win : (2048x1024) @ (1024x4096)
    sgemm_kernel<0><<<dim3(2 * DI / BN, MROWS / BM, 1), thr>>>(
        hidden, Win, xz, MROWS, 2 * DI, DM, DM, nullptr);

    // 2) causal depthwise conv + silu
    conv_silu_kernel<<<(MROWS * DI / 4) / 256, 256>>>(xz, dwk, dwb, xc);

    // 3) x_dbl = xc @ Wx : (2048x2048) @ (2048x96), split-K x8 + reduce
    sgemm_kernel<0><<<dim3(1, MROWS / BM, 8), thr>>>(
        xc, Wx, part, MROWS, NX, DI, DI, nullptr);
    reduce8_kernel<<<(MROWS * NX + 255) / 256, 256>>>(part, xdbl);

    // 4) delta = softplus(dt @ Wdt + bias) : (2048x64) @ (64x2048)
    sgemm_kernel<1><<<dim3(DI / BN, MROWS / BM, 1), thr>>>(
        xdbl, Wdt, dlt, MROWS, DI, DR, NX, dt_bias);

    // 5) selective scan (+ D skip + silu(z) gate)
    scan_kernel<<<256, 256>>>(xc, xdbl, dlt, xz, A_log, Dskip, yb);

    // 6) out = y @ Wout : (2048x2048) @ (2048x1024)
    sgemm_kernel<0><<<dim3(DM / BN, MROWS / BM, 1), thr>>>(
        yb, Wout, out, MROWS, DM, DI, DI, nullptr);
}

// round 5
// speedup vs baseline: 1.2281x; 1.2281x over previous
#include <cuda_runtime.h>
#include <cuda_bf16.h>
#include <cstdint>
#include <math.h>

// Problem constants
#define BB 2
#define LL 1024
#define DM 1024
#define DI 2048
#define DS 16
#define DR 64
#define NX 96          // DR + 2*DS
#define MROWS 2048     // B*L

typedef __nv_bfloat16 bf16;

// ---------------- scratch (device globals; no allocation allowed) -----------
__device__ float g_xz[(size_t)MROWS * 2 * DI];     // 2048 x 4096
__device__ float g_xc[(size_t)MROWS * DI];         // conv+silu output (fp32 for scan)
__device__ float g_xdbl[(size_t)MROWS * NX];       // 2048 x 96
__device__ float g_delta[(size_t)MROWS * DI];      // 2048 x 2048
__device__ float g_part[(size_t)8 * MROWS * NX];   // split-K partials for GEMM2

// Expanded-K bf16 operands: A' = [Ah | Al | Ah], B' = [Bh | Bh | Bl] along K.
__device__ bf16 g_WinT3[(size_t)4096 * 3072];
__device__ bf16 g_WxT3[(size_t)128 * 6144];        // N padded 96 -> 128
__device__ bf16 g_WdtT3[(size_t)2048 * 192];
__device__ bf16 g_WoutT3[(size_t)1024 * 6144];
__device__ bf16 g_h3[(size_t)2048 * 3072];
__device__ bf16 g_xc3[(size_t)2048 * 6144];
__device__ bf16 g_dt3[(size_t)2048 * 192];
__device__ bf16 g_y3[(size_t)2048 * 6144];

// ---------------- helpers ----------------------------------------------------
__device__ __forceinline__ uint32_t smem_u32(const void* p) {
    uint32_t a;
    asm("{ .reg .u64 t; cvta.to.shared.u64 t, %1; cvt.u32.u64 %0, t; }" : "=r"(a) : "l"(p));
    return a;
}
__device__ __forceinline__ void cp_async16(uint32_t dst, const void* src) {
    asm volatile("cp.async.cg.shared.global [%0], [%1], 16;" :: "r"(dst), "l"(src));
}
#define CP_COMMIT() asm volatile("cp.async.commit_group;" ::: "memory")
#define CP_WAIT2()  asm volatile("cp.async.wait_group 2;" ::: "memory")

__device__ __forceinline__ void ldsm_x4(uint32_t* r, uint32_t addr) {
    asm volatile("ldmatrix.sync.aligned.m8n8.x4.shared.b16 {%0,%1,%2,%3}, [%4];"
                 : "=r"(r[0]), "=r"(r[1]), "=r"(r[2]), "=r"(r[3]) : "r"(addr));
}
__device__ __forceinline__ void mma_16816(float* c, const uint32_t* a, uint32_t b0,
                                          uint32_t b1) {
    asm volatile(
        "mma.sync.aligned.m16n8k16.row.col.f32.bf16.bf16.f32 "
        "{%0,%1,%2,%3}, {%4,%5,%6,%7}, {%8,%9}, {%0,%1,%2,%3};"
        : "+f"(c[0]), "+f"(c[1]), "+f"(c[2]), "+f"(c[3])
        : "r"(a[0]), "r"(a[1]), "r"(a[2]), "r"(a[3]), "r"(b0), "r"(b1));
}

__device__ __forceinline__ float softplus_f(float v) {
    return fmaxf(v, 0.f) + log1pf(__expf(-fabsf(v)));
}
__device__ __forceinline__ void split_bf16(float v, bf16& h, bf16& l) {
    h = __float2bfloat16(v);
    l = __float2bfloat16(v - __bfloat162float(h));
}

// Swizzled smem byte offset inside a 128x32 bf16 tile (8KB).
// Physical: 64 rows of 128B; logical row r (0..127), k (0..31).
// slot = ((r&1)<<2)|(k>>3), swizzled slot ^= (r>>1)&7 -> LDSM conflict-free.
__device__ __forceinline__ uint32_t tile_off(int r, int k8) {
    const int prow = r >> 1;
    const int slot = (((r & 1) << 2) | (k8 >> 3)) ^ (prow & 7);
    return (uint32_t)((prow << 7) + (slot << 4));
}

// ---------------- mma.sync GEMM ----------------------------------------------
// C[M,N] (+= over z) = A'[M,K3] @ B'^T, both K-major bf16 (expanded-K layout).
// Block 128x128, K-chunk 32, 3-stage cp.async pipeline, 256 thr (8 warps 2mx4n).
// EPI: 0 plain fp32 store, 1 softplus(acc + bias[n]).
// Split-K: gridDim.z chunks the K' range; block z writes C + z*M*N.
template <int EPI>
__global__ __launch_bounds__(256) void mma_gemm(
    const bf16* __restrict__ A3, const bf16* __restrict__ B3,
    float* __restrict__ C, int N, int K3, int cpz,
    const float* __restrict__ bias) {
    __shared__ __align__(16) char smem[3 * 16384];   // 3 stages x (A 8KB + B 8KB)
    const uint32_t smu = smem_u32(smem);

    const int tid = threadIdx.x;
    const int lane = tid & 31;
    const int wid = tid >> 5;
    const int m0 = blockIdx.y * 128;
    const int n0 = blockIdx.x * 128;
    const int cbeg = blockIdx.z * cpz;
    float* __restrict__ Cb = C + (size_t)blockIdx.z * (size_t)MROWS * (size_t)N;

    const int wm0 = (wid & 1) * 64;    // warp m-origin in tile
    const int wn0 = (wid >> 1) * 32;   // warp n-origin in tile

    // g2s thread mapping: 512 16B chunks per tile; thread does c = tid, tid+256
    auto stage_load = [&](int s, int ck) {
        const int k0 = ck * 32;
        const uint32_t sa = smu + s * 16384;
        const uint32_t sb = sa + 8192;
#pragma unroll
        for (int h = 0; h < 2; ++h) {
            const int c = tid + h * 256;
            const int r = c >> 2, kc = c & 3;
            const uint32_t doff = tile_off(r, kc * 8);
            cp_async16(sa + doff, A3 + (size_t)(m0 + r) * K3 + k0 + kc * 8);
            cp_async16(sb + doff, B3 + (size_t)(n0 + r) * K3 + k0 + kc * 8);
        }
    };

    float acc[4][4][4];
#pragma unroll
    for (int i = 0; i < 4; ++i)
#pragma unroll
        for (int j = 0; j < 4; ++j)
#pragma unroll
            for (int q = 0; q < 4; ++q) acc[i][j][q] = 0.f;

    // prologue: fill 3 stages
#pragma unroll
    for (int p = 0; p < 3; ++p) {
        if (p < cpz) stage_load(p, cbeg + p);
        CP_COMMIT();
    }

    const int lr = lane & 7;
    const int lb1 = (lane >> 3) & 1;
    const int lb2 = lane >> 4;

    for (int j = 0; j < cpz; ++j) {
        const int s = j % 3;
        CP_WAIT2();
        __syncthreads();

        const uint32_t sa = smu + s * 16384;
        const uint32_t sb = sa + 8192;

        uint32_t a[4][2][4];
        uint32_t b[2][2][4];
#pragma unroll
        for (int mt = 0; mt < 4; ++mt)
#pragma unroll
            for (int kk = 0; kk < 2; ++kk) {
                const int r = wm0 + mt * 16 + lb1 * 8 + lr;
                const int k8 = kk * 16 + lb2 * 8;
                ldsm_x4(a[mt][kk], sa + tile_off(r, k8));
            }
#pragma unroll
        for (int nt = 0; nt < 2; ++nt)
#pragma unroll
            for (int kk = 0; kk < 2; ++kk) {
                const int r = wn0 + nt * 16 + lb2 * 8 + lr;
                const int k8 = kk * 16 + lb1 * 8;
                ldsm_x4(b[nt][kk], sb + tile_off(r, k8));
            }
        __syncthreads();

        if (j + 3 < cpz) stage_load(s, cbeg + j + 3);
        CP_COMMIT();

#pragma unroll
        for (int mt = 0; mt < 4; ++mt)
#pragma unroll
            for (int nt = 0; nt < 2; ++nt)
#pragma unroll
                for (int half = 0; half < 2; ++half)
#pragma unroll
                    for (int kk = 0; kk < 2; ++kk)
                        mma_16816(acc[mt][nt * 2 + half], a[mt][kk],
                                  b[nt][kk][half * 2], b[nt][kk][half * 2 + 1]);
    }

    // epilogue
    const int rbase = m0 + wm0 + (lane >> 2);
    const int cbase = n0 + wn0 + (lane & 3) * 2;
#pragma unroll
    for (int mt = 0; mt < 4; ++mt) {
#pragma unroll
        for (int nf = 0; nf < 4; ++nf) {
            const int row = rbase + mt * 16;
            const int col = cbase + nf * 8;
            if (col < N) {
                float v0 = acc[mt][nf][0], v1 = acc[mt][nf][1];
                float v2 = acc[mt][nf][2], v3 = acc[mt][nf][3];
                if (EPI == 1) {
                    const float b0 = bias[col], b1 = bias[col + 1];
                    v0 = softplus_f(v0 + b0); v1 = softplus_f(v1 + b1);
                    v2 = softplus_f(v2 + b0); v3 = softplus_f(v3 + b1);
                }
                *(float2*)&Cb[(size_t)row * N + col] = make_float2(v0, v1);
                *(float2*)&Cb[(size_t)(row + 8) * N + col] = make_float2(v2, v3);
            }
        }
    }
}

// ---------------- convert: W[K,N] fp32 -> B' [Npad, 3K] bf16 ----------------
__global__ __launch_bounds__(256) void convT_kernel(const float* __restrict__ W,
                                                    bf16* __restrict__ out,
                                                    int K, int N) {
    __shared__ float tile[32][33];
    const int k0 = blockIdx.x * 32, n0 = blockIdx.y * 32;
    const int tx = threadIdx.x, ty = threadIdx.y;  // 32 x 8
    const int K3 = 3 * K;
#pragma unroll
    for (int r = 0; r < 32; r += 8) {
        const int n = n0 + tx;
        tile[ty + r][tx] = (n < N) ? W[(size_t)(k0 + ty + r) * N + n] : 0.f;
    }
    __syncthreads();
#pragma unroll
    for (int r = 0; r < 32; r += 8) {
        const int n = n0 + ty + r, k = k0 + tx;
        const float v = tile[tx][ty + r];
        bf16 h, l; split_bf16(v, h, l);
        bf16* rowp = out + (size_t)n * K3;
        rowp[k] = h;          // pairs with A hi
        rowp[K + k] = h;      // pairs with A lo
        rowp[2 * K + k] = l;  // pairs with A hi
    }
}

// ---------------- convert: A[M,K] fp32 (lda) -> A' [M,3K] bf16 --------------
__global__ __launch_bounds__(256) void convA_kernel(const float* __restrict__ A,
                                                    bf16* __restrict__ out,
                                                    int K, int lda) {
    const int idx = blockIdx.x * blockDim.x + threadIdx.x;
    const int row = idx / (K / 4);
    const int c4 = (idx - row * (K / 4)) * 4;
    const int K3 = 3 * K;
    const float4 v = *reinterpret_cast<const float4*>(A + (size_t)row * lda + c4);
    bf16 h0, l0, h1, l1, h2, l2, h3, l3;
    split_bf16(v.x, h0, l0); split_bf16(v.y, h1, l1);
    split_bf16(v.z, h2, l2); split_bf16(v.w, h3, l3);
    bf16* rowp = out + (size_t)row * K3;
    __nv_bfloat162* H0 = reinterpret_cast<__nv_bfloat162*>(rowp + c4);
    __nv_bfloat162* L  = reinterpret_cast<__nv_bfloat162*>(rowp + K + c4);
    __nv_bfloat162* H1 = reinterpret_cast<__nv_bfloat162*>(rowp + 2 * K + c4);
    H0[0] = __nv_bfloat162(h0, h1); H0[1] = __nv_bfloat162(h2, h3);
    L[0]  = __nv_bfloat162(l0, l1); L[1]  = __nv_bfloat162(l2, l3);
    H1[0] = __nv_bfloat162(h0, h1); H1[1] = __nv_bfloat162(h2, h3);
}

// ---------------- causal depthwise conv (k=4) + SiLU + A'-split -------------
__global__ __launch_bounds__(256) void conv_silu_kernel(
    const float* __restrict__ xz, const float* __restrict__ kern,
    const float* __restrict__ kb, float* __restrict__ xc,
    bf16* __restrict__ xc3) {
    const int idx = blockIdx.x * blockDim.x + threadIdx.x;
    const int d4 = idx & (DI / 4 - 1);
    const int row = idx / (DI / 4);
    const int l = row & (LL - 1);
    const int d = d4 * 4;

    float4 acc = *(const float4*)(kb + d);
#pragma unroll
    for (int i = 0; i < 4; ++i) {
        const int ll = l - 3 + i;
        if (ll >= 0) {
            const float4 x4 = *(const float4*)(xz + (size_t)(row - 3 + i) * (2 * DI) + d);
            const float4 k4 = *(const float4*)(kern + i * DI + d);
            acc.x = fmaf(x4.x, k4.x, acc.x);
            acc.y = fmaf(x4.y, k4.y, acc.y);
            acc.z = fmaf(x4.z, k4.z, acc.z);
            acc.w = fmaf(x4.w, k4.w, acc.w);
        }
    }
    acc.x = acc.x / (1.f + __expf(-acc.x));
    acc.y = acc.y / (1.f + __expf(-acc.y));
    acc.z = acc.z / (1.f + __expf(-acc.z));
    acc.w = acc.w / (1.f + __expf(-acc.w));
    *(float4*)(xc + (size_t)row * DI + d) = acc;

    bf16 h0, l0, h1, l1, h2, l2, h3, l3;
    split_bf16(acc.x, h0, l0); split_bf16(acc.y, h1, l1);
    split_bf16(acc.z, h2, l2); split_bf16(acc.w, h3, l3);
    bf16* rowp = xc3 + (size_t)row * (3 * DI);
    __nv_bfloat162* H0 = reinterpret_cast<__nv_bfloat162*>(rowp + d);
    __nv_bfloat162* L  = reinterpret_cast<__nv_bfloat162*>(rowp + DI + d);
    __nv_bfloat162* H1 = reinterpret_cast<__nv_bfloat162*>(rowp + 2 * DI + d);
    H0[0] = __nv_bfloat162(h0, h1); H0[1] = __nv_bfloat162(h2, h3);
    L[0]  = __nv_bfloat162(l0, l1); L[1]  = __nv_bfloat162(l2, l3);
    H1[0] = __nv_bfloat162(h0, h1); H1[1] = __nv_bfloat162(h2, h3);
}

// ---------------- split-K reduce (deterministic) ----------------------------
__global__ __launch_bounds__(256) void reduce8_kernel(const float* __restrict__ part,
                                                      float* __restrict__ out) {
    const int i = blockIdx.x * blockDim.x + threadIdx.x;
    if (i < MROWS * NX) {
        float s = 0.f;
#pragma unroll
        for (int c = 0; c < 8; ++c) s += part[(size_t)c * (MROWS * NX) + i];
        out[i] = s;
    }
}

// ---------------- selective scan (writes y in A' layout) --------------------
__global__ __launch_bounds__(256) void scan_kernel(
    const float* __restrict__ xc, const float* __restrict__ xdbl,
    const float* __restrict__ delta, const float* __restrict__ xz,
    const float* __restrict__ A_log, const float* __restrict__ Dskip,
    bf16* __restrict__ y3) {
    const int w = blockIdx.x * 8 + (threadIdx.x >> 5);
    const int lane = threadIdx.x & 31;
    const int b = w >> 10;
    const int dp = w & 1023;
    const int n = lane & 15;
    const int d = dp * 2 + (lane >> 4);

    const float An = -expf(A_log[d * DS + n]);
    const float Dv = Dskip[d];

    const size_t rb = (size_t)(b << 10);
    const float* __restrict__ dptr = delta + rb * DI + d;
    const float* __restrict__ uptr = xc + rb * DI + d;
    const float* __restrict__ zptr = xz + rb * (2 * DI) + DI + d;
    const float* __restrict__ bcb = xdbl + rb * NX;
    bf16* __restrict__ yp = y3 + rb * (3 * DI) + d;

    float st = 0.f;
#pragma unroll 2
    for (int l = 0; l < LL; ++l) {
        const float dl = __ldg(dptr + (size_t)l * DI);
        const float u = __ldg(uptr + (size_t)l * DI);
        const float Bn = __ldg(bcb + (size_t)l * NX + DR + n);
        const float Cn = __ldg(bcb + (size_t)l * NX + DR + DS + n);
        const float dA = __expf(dl * An);
        st = fmaf(dA, st, dl * u * Bn);
        float c = st * Cn;
        c += __shfl_xor_sync(0xffffffffu, c, 8);
        c += __shfl_xor_sync(0xffffffffu, c, 4);
        c += __shfl_xor_sync(0xffffffffu, c, 2);
        c += __shfl_xor_sync(0xffffffffu, c, 1);
        if (n == 0) {
            const float zv = __ldg(zptr + (size_t)l * (2 * DI));
            const float yv = fmaf(u, Dv, c) * zv / (1.f + __expf(-zv));
            bf16 h, lo2; split_bf16(yv, h, lo2);
            bf16* rowp = yp + (size_t)l * (3 * DI);
            rowp[0] = h;
            rowp[DI] = lo2;
            rowp[2 * DI] = h;
        }
    }
}

// ---------------- launch ----------------------------------------------------
extern "C" void kernel_launch(void* const* d_in, const int* in_sizes, int n_in,
                              void* d_out, int out_size) {
    (void)in_sizes; (void)n_in; (void)out_size;
    const float* hidden = (const float*)d_in[0];
    const float* Win = (const float*)d_in[1];
    const float* Wx = (const float*)d_in[2];
    const float* Wdt = (const float*)d_in[3];
    const float* dt_bias = (const float*)d_in[4];
    const float* Wout = (const float*)d_in[5];
    const float* dwk = (const float*)d_in[6];
    const float* dwb = (const float*)d_in[7];
    const float* A_log = (const float*)d_in[8];
    const float* Dskip = (const float*)d_in[9];
    float* out = (float*)d_out;

    float *xz, *xc, *xdbl, *dlt, *part;
    cudaGetSymbolAddress((void**)&xz, g_xz);
    cudaGetSymbolAddress((void**)&xc, g_xc);
    cudaGetSymbolAddress((void**)&xdbl, g_xdbl);
    cudaGetSymbolAddress((void**)&dlt, g_delta);
    cudaGetSymbolAddress((void**)&part, g_part);

    bf16 *WinT3, *WxT3, *WdtT3, *WoutT3, *h3, *xc3, *dt3, *y3;
    cudaGetSymbolAddress((void**)&WinT3, g_WinT3);
    cudaGetSymbolAddress((void**)&WxT3, g_WxT3);
    cudaGetSymbolAddress((void**)&WdtT3, g_WdtT3);
    cudaGetSymbolAddress((void**)&WoutT3, g_WoutT3);
    cudaGetSymbolAddress((void**)&h3, g_h3);
    cudaGetSymbolAddress((void**)&xc3, g_xc3);
    cudaGetSymbolAddress((void**)&dt3, g_dt3);
    cudaGetSymbolAddress((void**)&y3, g_y3);

    const dim3 tb(32, 8);

    // weight transposes + hi/lo splits into expanded-K layout
    convT_kernel<<<dim3(DM / 32, 4096 / 32), tb>>>(Win, WinT3, DM, 2 * DI);
    convT_kernel<<<dim3(DI / 32, 128 / 32), tb>>>(Wx, WxT3, DI, NX);
    convT_kernel<<<dim3(DR / 32, DI / 32), tb>>>(Wdt, WdtT3, DR, DI);
    convT_kernel<<<dim3(DI / 32, DM / 32), tb>>>(Wout, WoutT3, DI, DM);

    // hidden -> A' layout
    convA_kernel<<<(MROWS * DM / 4) / 256, 256>>>(hidden, h3, DM, DM);

    // GEMM1: xz = hidden @ Win  (M=2048, N=4096, K'=3072)
    mma_gemm<0><<<dim3(4096 / 128, MROWS / 128, 1), 256>>>(
        h3, WinT3, xz, 2 * DI, 3 * DM, 3 * DM / 32, nullptr);

    // conv + silu (+ A'-split of xc)
    conv_silu_kernel<<<(MROWS * DI / 4) / 256, 256>>>(xz, dwk, dwb, xc, xc3);

    // GEMM2: x_dbl = xc @ Wx  (N=96, K'=6144), split-K x8 + reduce
    mma_gemm<0><<<dim3(1, MROWS / 128, 8), 256>>>(
        xc3, WxT3, part, NX, 3 * DI, (3 * DI / 32) / 8, nullptr);
    reduce8_kernel<<<(MROWS * NX + 255) / 256, 256>>>(part, xdbl);

    // dt slice -> A' layout (K=64, lda=96)
    convA_kernel<<<(MROWS * DR / 4) / 256, 256>>>(xdbl, dt3, DR, NX);

    // GEMM3: delta = softplus(dt @ Wdt + bias)  (N=2048, K'=192)
    mma_gemm<1><<<dim3(DI / 128, MROWS / 128, 1), 256>>>(
        dt3, WdtT3, dlt, DI, 3 * DR, 3 * DR / 32, dt_bias);

    // selective scan -> y in A' layout
    scan_kernel<<<256, 256>>>(xc, xdbl, dlt, xz, A_log, Dskip, y3);

    // GEMM4: out = y @ Wout  (N=1024, K'=6144)
    mma_gemm<0><<<dim3(DM / 128, MROWS / 128, 1), 256>>>(
        y3, WoutT3, out, DM, 3 * DI, 3 * DI / 32, nullptr);
}

// round 7
// speedup vs baseline: 1.3266x; 1.0802x over previous
#include <cuda_runtime.h>
#include <cuda_bf16.h>
#include <cstdint>
#include <math.h>

// Problem constants
#define BB 2
#define LL 1024
#define DM 1024
#define DI 2048
#define DS 16
#define DR 64
#define NX 96          // DR + 2*DS
#define MROWS 2048     // B*L

typedef __nv_bfloat16 bf16;

// ---------------- scratch (device globals; no allocation allowed) -----------
__device__ float g_xz[(size_t)MROWS * 2 * DI];     // 2048 x 4096
__device__ float g_xc[(size_t)MROWS * DI];         // conv+silu output (fp32 for scan)
__device__ float g_xdbl[(size_t)MROWS * NX];       // 2048 x 96
__device__ float g_delta[(size_t)MROWS * DI];      // 2048 x 2048
__device__ float g_part[(size_t)8 * MROWS * NX];   // split-K partials for GEMM2

// Expanded-K bf16 operands: A' = [Ah | Al | Ah], B' = [Bh | Bh | Bl] along K.
__device__ bf16 g_WinT3[(size_t)4096 * 3072];
__device__ bf16 g_WxT3[(size_t)128 * 6144];        // N padded 96 -> 128
__device__ bf16 g_WdtT3[(size_t)2048 * 192];
__device__ bf16 g_WoutT3[(size_t)1024 * 6144];
__device__ bf16 g_h3[(size_t)2048 * 3072];
__device__ bf16 g_xc3[(size_t)2048 * 6144];
__device__ bf16 g_dt3[(size_t)2048 * 192];
__device__ bf16 g_y3[(size_t)2048 * 6144];

// ---------------- helpers ----------------------------------------------------
__device__ __forceinline__ uint32_t smem_u32(const void* p) {
    uint32_t a;
    asm("{ .reg .u64 t; cvta.to.shared.u64 t, %1; cvt.u32.u64 %0, t; }" : "=r"(a) : "l"(p));
    return a;
}
__device__ __forceinline__ void cp_async16(uint32_t dst, const void* src) {
    asm volatile("cp.async.cg.shared.global [%0], [%1], 16;" :: "r"(dst), "l"(src));
}
#define CP_COMMIT() asm volatile("cp.async.commit_group;" ::: "memory")
#define CP_WAIT2()  asm volatile("cp.async.wait_group 2;" ::: "memory")

__device__ __forceinline__ void ldsm_x4(uint32_t* r, uint32_t addr) {
    asm volatile("ldmatrix.sync.aligned.m8n8.x4.shared.b16 {%0,%1,%2,%3}, [%4];"
                 : "=r"(r[0]), "=r"(r[1]), "=r"(r[2]), "=r"(r[3]) : "r"(addr));
}
__device__ __forceinline__ void mma_16816(float* c, const uint32_t* a, uint32_t b0,
                                          uint32_t b1) {
    asm volatile(
        "mma.sync.aligned.m16n8k16.row.col.f32.bf16.bf16.f32 "
        "{%0,%1,%2,%3}, {%4,%5,%6,%7}, {%8,%9}, {%0,%1,%2,%3};"
        : "+f"(c[0]), "+f"(c[1]), "+f"(c[2]), "+f"(c[3])
        : "r"(a[0]), "r"(a[1]), "r"(a[2]), "r"(a[3]), "r"(b0), "r"(b1));
}

__device__ __forceinline__ float softplus_f(float v) {
    return fmaxf(v, 0.f) + log1pf(__expf(-fabsf(v)));
}
__device__ __forceinline__ void split_bf16(float v, bf16& h, bf16& l) {
    h = __float2bfloat16(v);
    l = __float2bfloat16(v - __bfloat162float(h));
}

// Swizzled smem byte offset inside a 128x32 bf16 tile (8KB).
// Physical: 64 rows of 128B; logical row r (0..127), k (0..31).
// slot = ((r&1)<<2)|(k>>3), swizzled slot ^= (r>>1)&7 -> LDSM conflict-free.
__device__ __forceinline__ uint32_t tile_off(int r, int k8) {
    const int prow = r >> 1;
    const int slot = (((r & 1) << 2) | (k8 >> 3)) ^ (prow & 7);
    return (uint32_t)((prow << 7) + (slot << 4));
}

// ---------------- mma.sync GEMM ----------------------------------------------
// C[M,N] (+= over z) = A'[M,K3] @ B'^T, both K-major bf16 (expanded-K layout).
// Block 128x128, K-chunk 32, 4-stage cp.async pipeline (distance 3), ONE
// __syncthreads per chunk, per-kk fragment loads, 2 CTAs/SM.
// EPI: 0 plain fp32 store, 1 softplus(acc + bias[n]).
// Split-K: gridDim.z chunks the K' range; block z writes C + z*M*N.
#define STAGE_B 16384
#define GSMEM (4 * STAGE_B)

template <int EPI>
__global__ __launch_bounds__(256, 2) void mma_gemm(
    const bf16* __restrict__ A3, const bf16* __restrict__ B3,
    float* __restrict__ C, int N, int K3, int cpz,
    const float* __restrict__ bias) {
    extern __shared__ __align__(16) char smem[];
    const uint32_t smu = smem_u32(smem);

    const int tid = threadIdx.x;
    const int lane = tid & 31;
    const int wid = tid >> 5;
    const int m0 = blockIdx.y * 128;
    const int n0 = blockIdx.x * 128;
    const int cbeg = blockIdx.z * cpz;
    float* __restrict__ Cb = C + (size_t)blockIdx.z * (size_t)MROWS * (size_t)N;

    const int wm0 = (wid & 1) * 64;    // warp m-origin in tile
    const int wn0 = (wid >> 1) * 32;   // warp n-origin in tile

    // g2s mapping: 512 16B chunks per tile; thread covers c = tid, tid+256.
    const int gr0 = tid >> 2, gkc = (tid & 3) * 8;
    const uint32_t d0 = tile_off(gr0, gkc);
    const uint32_t d1 = tile_off(gr0 + 64, gkc);
    const bf16* Ag = A3 + (size_t)(m0 + gr0) * K3 + gkc;
    const bf16* Ag2 = A3 + (size_t)(m0 + gr0 + 64) * K3 + gkc;
    const bf16* Bg = B3 + (size_t)(n0 + gr0) * K3 + gkc;
    const bf16* Bg2 = B3 + (size_t)(n0 + gr0 + 64) * K3 + gkc;

    auto stage_load = [&](int s, int ck) {
        const int k0 = ck * 32;
        const uint32_t sa = smu + s * STAGE_B;
        const uint32_t sb = sa + 8192;
        cp_async16(sa + d0, Ag + k0);
        cp_async16(sa + d1, Ag2 + k0);
        cp_async16(sb + d0, Bg + k0);
        cp_async16(sb + d1, Bg2 + k0);
    };

    float acc[4][4][4];
#pragma unroll
    for (int i = 0; i < 4; ++i)
#pragma unroll
        for (int j = 0; j < 4; ++j)
#pragma unroll
            for (int q = 0; q < 4; ++q) acc[i][j][q] = 0.f;

    // prologue: chunks 0..2 into stages 0..2
#pragma unroll
    for (int p = 0; p < 3; ++p) {
        if (p < cpz) stage_load(p, cbeg + p);
        CP_COMMIT();
    }

    const int lr = lane & 7;
    const int lb1 = (lane >> 3) & 1;
    const int lb2 = lane >> 4;
    // Per-fragment swizzled offsets are k-invariant up to the k8 term; precompute rows.
    const int ar[4] = {wm0 + 0 + lb1 * 8 + lr, wm0 + 16 + lb1 * 8 + lr,
                       wm0 + 32 + lb1 * 8 + lr, wm0 + 48 + lb1 * 8 + lr};
    const int br[2] = {wn0 + 0 + lb2 * 8 + lr, wn0 + 16 + lb2 * 8 + lr};

    for (int j = 0; j < cpz; ++j) {
        const int s = j & 3;
        CP_WAIT2();          // chunks <= j resident
        __syncthreads();     // all warps done reading stage (j+3)&3's old contents

        if (j + 3 < cpz) stage_load((j + 3) & 3, cbeg + j + 3);
        CP_COMMIT();

        const uint32_t sa = smu + s * STAGE_B;
        const uint32_t sb = sa + 8192;
#pragma unroll
        for (int kk = 0; kk < 2; ++kk) {
            uint32_t a[4][4], b[2][4];
            const int ka = kk * 16 + lb2 * 8;
            const int kb = kk * 16 + lb1 * 8;
#pragma unroll
            for (int mt = 0; mt < 4; ++mt) ldsm_x4(a[mt], sa + tile_off(ar[mt], ka));
#pragma unroll
            for (int nt = 0; nt < 2; ++nt) ldsm_x4(b[nt], sb + tile_off(br[nt], kb));
#pragma unroll
            for (int mt = 0; mt < 4; ++mt)
#pragma unroll
                for (int nt = 0; nt < 2; ++nt)
#pragma unroll
                    for (int half = 0; half < 2; ++half)
                        mma_16816(acc[mt][nt * 2 + half], a[mt],
                                  b[nt][half * 2], b[nt][half * 2 + 1]);
        }
    }

    // epilogue
    const int rbase = m0 + wm0 + (lane >> 2);
    const int cbase = n0 + wn0 + (lane & 3) * 2;
#pragma unroll
    for (int mt = 0; mt < 4; ++mt) {
#pragma unroll
        for (int nf = 0; nf < 4; ++nf) {
            const int row = rbase + mt * 16;
            const int col = cbase + nf * 8;
            if (col < N) {
                float v0 = acc[mt][nf][0], v1 = acc[mt][nf][1];
                float v2 = acc[mt][nf][2], v3 = acc[mt][nf][3];
                if (EPI == 1) {
                    const float b0 = bias[col], b1 = bias[col + 1];
                    v0 = softplus_f(v0 + b0); v1 = softplus_f(v1 + b1);
                    v2 = softplus_f(v2 + b0); v3 = softplus_f(v3 + b1);
                }
                *(float2*)&Cb[(size_t)row * N + col] = make_float2(v0, v1);
                *(float2*)&Cb[(size_t)(row + 8) * N + col] = make_float2(v2, v3);
            }
        }
    }
}

// ---------------- convert: W[K,N] fp32 -> B' [Npad, 3K] bf16 ----------------
__global__ __launch_bounds__(256) void convT_kernel(const float* __restrict__ W,
                                                    bf16* __restrict__ out,
                                                    int K, int N) {
    __shared__ float tile[32][33];
    const int k0 = blockIdx.x * 32, n0 = blockIdx.y * 32;
    const int tx = threadIdx.x, ty = threadIdx.y;  // 32 x 8
    const int K3 = 3 * K;
#pragma unroll
    for (int r = 0; r < 32; r += 8) {
        const int n = n0 + tx;
        tile[ty + r][tx] = (n < N) ? W[(size_t)(k0 + ty + r) * N + n] : 0.f;
    }
    __syncthreads();
#pragma unroll
    for (int r = 0; r < 32; r += 8) {
        const int n = n0 + ty + r, k = k0 + tx;
        const float v = tile[tx][ty + r];
        bf16 h, l; split_bf16(v, h, l);
        bf16* rowp = out + (size_t)n * K3;
        rowp[k] = h;          // pairs with A hi
        rowp[K + k] = h;      // pairs with A lo
        rowp[2 * K + k] = l;  // pairs with A hi
    }
}

// ---------------- convert: A[M,K] fp32 (lda) -> A' [M,3K] bf16 --------------
__global__ __launch_bounds__(256) void convA_kernel(const float* __restrict__ A,
                                                    bf16* __restrict__ out,
                                                    int K, int lda) {
    const int idx = blockIdx.x * blockDim.x + threadIdx.x;
    const int row = idx / (K / 4);
    const int c4 = (idx - row * (K / 4)) * 4;
    const int K3 = 3 * K;
    const float4 v = *reinterpret_cast<const float4*>(A + (size_t)row * lda + c4);
    bf16 h0, l0, h1, l1, h2, l2, h3, l3;
    split_bf16(v.x, h0, l0); split_bf16(v.y, h1, l1);
    split_bf16(v.z, h2, l2); split_bf16(v.w, h3, l3);
    bf16* rowp = out + (size_t)row * K3;
    __nv_bfloat162* H0 = reinterpret_cast<__nv_bfloat162*>(rowp + c4);
    __nv_bfloat162* L  = reinterpret_cast<__nv_bfloat162*>(rowp + K + c4);
    __nv_bfloat162* H1 = reinterpret_cast<__nv_bfloat162*>(rowp + 2 * K + c4);
    H0[0] = __nv_bfloat162(h0, h1); H0[1] = __nv_bfloat162(h2, h3);
    L[0]  = __nv_bfloat162(l0, l1); L[1]  = __nv_bfloat162(l2, l3);
    H1[0] = __nv_bfloat162(h0, h1); H1[1] = __nv_bfloat162(h2, h3);
}

// ---------------- causal depthwise conv (k=4) + SiLU + A'-split -------------
__global__ __launch_bounds__(256) void conv_silu_kernel(
    const float* __restrict__ xz, const float* __restrict__ kern,
    const float* __restrict__ kb, float* __restrict__ xc,
    bf16* __restrict__ xc3) {
    const int idx = blockIdx.x * blockDim.x + threadIdx.x;
    const int d4 = idx & (DI / 4 - 1);
    const int row = idx / (DI / 4);
    const int l = row & (LL - 1);
    const int d = d4 * 4;

    float4 acc = *(const float4*)(kb + d);
#pragma unroll
    for (int i = 0; i < 4; ++i) {
        const int ll = l - 3 + i;
        if (ll >= 0) {
            const float4 x4 = *(const float4*)(xz + (size_t)(row - 3 + i) * (2 * DI) + d);
            const float4 k4 = *(const float4*)(kern + i * DI + d);
            acc.x = fmaf(x4.x, k4.x, acc.x);
            acc.y = fmaf(x4.y, k4.y, acc.y);
            acc.z = fmaf(x4.z, k4.z, acc.z);
            acc.w = fmaf(x4.w, k4.w, acc.w);
        }
    }
    acc.x = acc.x * __fdividef(1.f, 1.f + __expf(-acc.x));
    acc.y = acc.y * __fdividef(1.f, 1.f + __expf(-acc.y));
    acc.z = acc.z * __fdividef(1.f, 1.f + __expf(-acc.z));
    acc.w = acc.w * __fdividef(1.f, 1.f + __expf(-acc.w));
    *(float4*)(xc + (size_t)row * DI + d) = acc;

    bf16 h0, l0, h1, l1, h2, l2, h3, l3;
    split_bf16(acc.x, h0, l0); split_bf16(acc.y, h1, l1);
    split_bf16(acc.z, h2, l2); split_bf16(acc.w, h3, l3);
    bf16* rowp = xc3 + (size_t)row * (3 * DI);
    __nv_bfloat162* H0 = reinterpret_cast<__nv_bfloat162*>(rowp + d);
    __nv_bfloat162* L  = reinterpret_cast<__nv_bfloat162*>(rowp + DI + d);
    __nv_bfloat162* H1 = reinterpret_cast<__nv_bfloat162*>(rowp + 2 * DI + d);
    H0[0] = __nv_bfloat162(h0, h1); H0[1] = __nv_bfloat162(h2, h3);
    L[0]  = __nv_bfloat162(l0, l1); L[1]  = __nv_bfloat162(l2, l3);
    H1[0] = __nv_bfloat162(h0, h1); H1[1] = __nv_bfloat162(h2, h3);
}

// ---------------- split-K reduce (deterministic) ----------------------------
__global__ __launch_bounds__(256) void reduce8_kernel(const float* __restrict__ part,
                                                      float* __restrict__ out) {
    const int i = blockIdx.x * blockDim.x + threadIdx.x;
    if (i < MROWS * NX) {
        float s = 0.f;
#pragma unroll
        for (int c = 0; c < 8; ++c) s += part[(size_t)c * (MROWS * NX) + i];
        out[i] = s;
    }
}

// ---------------- selective scan (writes y in A' layout) --------------------
__global__ __launch_bounds__(256) void scan_kernel(
    const float* __restrict__ xc, const float* __restrict__ xdbl,
    const float* __restrict__ delta, const float* __restrict__ xz,
    const float* __restrict__ A_log, const float* __restrict__ Dskip,
    bf16* __restrict__ y3) {
    const int w = blockIdx.x * 8 + (threadIdx.x >> 5);
    const int lane = threadIdx.x & 31;
    const int b = w >> 10;
    const int dp = w & 1023;
    const int n = lane & 15;
    const int d = dp * 2 + (lane >> 4);

    const float An = -expf(A_log[d * DS + n]);
    const float Dv = Dskip[d];

    const size_t rb = (size_t)(b << 10);
    const float* __restrict__ dptr = delta + rb * DI + d;
    const float* __restrict__ uptr = xc + rb * DI + d;
    const float* __restrict__ zptr = xz + rb * (2 * DI) + DI + d;
    const float* __restrict__ bcb = xdbl + rb * NX;
    bf16* __restrict__ yp = y3 + rb * (3 * DI) + d;

    float st = 0.f;
#pragma unroll 4
    for (int l = 0; l < LL; ++l) {
        const float dl = __ldg(dptr + (size_t)l * DI);
        const float u = __ldg(uptr + (size_t)l * DI);
        const float Bn = __ldg(bcb + (size_t)l * NX + DR + n);
        const float Cn = __ldg(bcb + (size_t)l * NX + DR + DS + n);
        const float dA = __expf(dl * An);
        st = fmaf(dA, st, dl * u * Bn);
        float c = st * Cn;
        c += __shfl_xor_sync(0xffffffffu, c, 8);
        c += __shfl_xor_sync(0xffffffffu, c, 4);
        c += __shfl_xor_sync(0xffffffffu, c, 2);
        c += __shfl_xor_sync(0xffffffffu, c, 1);
        if (n == 0) {
            const float zv = __ldg(zptr + (size_t)l * (2 * DI));
            const float yv = fmaf(u, Dv, c) * zv * __fdividef(1.f, 1.f + __expf(-zv));
            bf16 h, lo2; split_bf16(yv, h, lo2);
            bf16* rowp = yp + (size_t)l * (3 * DI);
            rowp[0] = h;
            rowp[DI] = lo2;
            rowp[2 * DI] = h;
        }
    }
}

// ---------------- launch ----------------------------------------------------
extern "C" void kernel_launch(void* const* d_in, const int* in_sizes, int n_in,
                              void* d_out, int out_size) {
    (void)in_sizes; (void)n_in; (void)out_size;
    const float* hidden = (const float*)d_in[0];
    const float* Win = (const float*)d_in[1];
    const float* Wx = (const float*)d_in[2];
    const float* Wdt = (const float*)d_in[3];
    const float* dt_bias = (const float*)d_in[4];
    const float* Wout = (const float*)d_in[5];
    const float* dwk = (const float*)d_in[6];
    const float* dwb = (const float*)d_in[7];
    const float* A_log = (const float*)d_in[8];
    const float* Dskip = (const float*)d_in[9];
    float* out = (float*)d_out;

    float *xz, *xc, *xdbl, *dlt, *part;
    cudaGetSymbolAddress((void**)&xz, g_xz);
    cudaGetSymbolAddress((void**)&xc, g_xc);
    cudaGetSymbolAddress((void**)&xdbl, g_xdbl);
    cudaGetSymbolAddress((void**)&dlt, g_delta);
    cudaGetSymbolAddress((void**)&part, g_part);

    bf16 *WinT3, *WxT3, *WdtT3, *WoutT3, *h3, *xc3, *dt3, *y3;
    cudaGetSymbolAddress((void**)&WinT3, g_WinT3);
    cudaGetSymbolAddress((void**)&WxT3, g_WxT3);
    cudaGetSymbolAddress((void**)&WdtT3, g_WdtT3);
    cudaGetSymbolAddress((void**)&WoutT3, g_WoutT3);
    cudaGetSymbolAddress((void**)&h3, g_h3);
    cudaGetSymbolAddress((void**)&xc3, g_xc3);
    cudaGetSymbolAddress((void**)&dt3, g_dt3);
    cudaGetSymbolAddress((void**)&y3, g_y3);

    cudaFuncSetAttribute(mma_gemm<0>, cudaFuncAttributeMaxDynamicSharedMemorySize, GSMEM);
    cudaFuncSetAttribute(mma_gemm<1>, cudaFuncAttributeMaxDynamicSharedMemorySize, GSMEM);

    const dim3 tb(32, 8);

    // weight transposes + hi/lo splits into expanded-K layout
    convT_kernel<<<dim3(DM / 32, 4096 / 32), tb>>>(Win, WinT3, DM, 2 * DI);
    convT_kernel<<<dim3(DI / 32, 128 / 32), tb>>>(Wx, WxT3, DI, NX);
    convT_kernel<<<dim3(DR / 32, DI / 32), tb>>>(Wdt, WdtT3, DR, DI);
    convT_kernel<<<dim3(DI / 32, DM / 32), tb>>>(Wout, WoutT3, DI, DM);

    // hidden -> A' layout
    convA_kernel<<<(MROWS * DM / 4) / 256, 256>>>(hidden, h3, DM, DM);

    // GEMM1: xz = hidden @ Win  (M=2048, N=4096, K'=3072)  [launch index 5]
    mma_gemm<0><<<dim3(4096 / 128, MROWS / 128, 1), 256, GSMEM>>>(
        h3, WinT3, xz, 2 * DI, 3 * DM, 3 * DM / 32, nullptr);

    // conv + silu (+ A'-split of xc)
    conv_silu_kernel<<<(MROWS * DI / 4) / 256, 256>>>(xz, dwk, dwb, xc, xc3);

    // GEMM2: x_dbl = xc @ Wx  (N=96, K'=6144), split-K x8 + reduce
    mma_gemm<0><<<dim3(1, MROWS / 128, 8), 256, GSMEM>>>(
        xc3, WxT3, part, NX, 3 * DI, (3 * DI / 32) / 8, nullptr);
    reduce8_kernel<<<(MROWS * NX + 255) / 256, 256>>>(part, xdbl);

    // dt slice -> A' layout (K=64, lda=96)
    convA_kernel<<<(MROWS * DR / 4) / 256, 256>>>(xdbl, dt3, DR, NX);

    // GEMM3: delta = softplus(dt @ Wdt + bias)  (N=2048, K'=192)
    mma_gemm<1><<<dim3(DI / 128, MROWS / 128, 1), 256, GSMEM>>>(
        dt3, WdtT3, dlt, DI, 3 * DR, 3 * DR / 32, dt_bias);

    // selective scan -> y in A' layout
    scan_kernel<<<256, 256>>>(xc, xdbl, dlt, xz, A_log, Dskip, y3);

    // GEMM4: out = y @ Wout  (N=1024, K'=6144)
    mma_gemm<0><<<dim3(DM / 128, MROWS / 128, 1), 256, GSMEM>>>(
        y3, WoutT3, out, DM, 3 * DI, 3 * DI / 32, nullptr);
}

// round 8
// speedup vs baseline: 2.6187x; 1.9740x over previous
#include <cuda_runtime.h>
#include <cuda_fp16.h>
#include <cstdint>
#include <math.h>

// Problem constants
#define BB 2
#define LL 1024
#define DM 1024
#define DI 2048
#define DS 16
#define DR 64
#define NX 96          // DR + 2*DS
#define MROWS 2048     // B*L

// ---------------- scratch (device globals; no allocation allowed) -----------
__device__ float g_xz[(size_t)MROWS * 2 * DI];     // 2048 x 4096
__device__ float g_xdbl[(size_t)MROWS * NX];       // 2048 x 96
__device__ float g_delta[(size_t)MROWS * DI];      // 2048 x 2048
__device__ float g_part[(size_t)8 * MROWS * NX];   // split-K partials for GEMM2

// Expanded-K fp16 operands: A' = [Ah | Al], B' = [Bh | Bh] along K (K' = 2K).
__device__ __half g_WinT2[(size_t)4096 * 2048];
__device__ __half g_WxT2[(size_t)128 * 4096];      // N padded 96 -> 128
__device__ __half g_WdtT2[(size_t)2048 * 128];
__device__ __half g_WoutT2[(size_t)1024 * 4096];
__device__ __half g_h2[(size_t)2048 * 2048];
__device__ __half g_xc2[(size_t)2048 * 4096];      // conv+silu out, [Ah|Al]
__device__ __half g_dt2[(size_t)2048 * 128];
__device__ __half g_y2[(size_t)2048 * 4096];

// ---------------- helpers ----------------------------------------------------
__device__ __forceinline__ uint32_t smem_u32(const void* p) {
    uint32_t a;
    asm("{ .reg .u64 t; cvta.to.shared.u64 t, %1; cvt.u32.u64 %0, t; }" : "=r"(a) : "l"(p));
    return a;
}
__device__ __forceinline__ void cp_async16(uint32_t dst, const void* src) {
    asm volatile("cp.async.cg.shared.global [%0], [%1], 16;" :: "r"(dst), "l"(src));
}
#define CP_COMMIT() asm volatile("cp.async.commit_group;" ::: "memory")
#define CP_WAIT2()  asm volatile("cp.async.wait_group 2;" ::: "memory")

__device__ __forceinline__ void ldsm_x4(uint32_t* r, uint32_t addr) {
    asm volatile("ldmatrix.sync.aligned.m8n8.x4.shared.b16 {%0,%1,%2,%3}, [%4];"
                 : "=r"(r[0]), "=r"(r[1]), "=r"(r[2]), "=r"(r[3]) : "r"(addr));
}
__device__ __forceinline__ void mma_16816(float* c, const uint32_t* a, uint32_t b0,
                                          uint32_t b1) {
    asm volatile(
        "mma.sync.aligned.m16n8k16.row.col.f32.f16.f16.f32 "
        "{%0,%1,%2,%3}, {%4,%5,%6,%7}, {%8,%9}, {%0,%1,%2,%3};"
        : "+f"(c[0]), "+f"(c[1]), "+f"(c[2]), "+f"(c[3])
        : "r"(a[0]), "r"(a[1]), "r"(a[2]), "r"(a[3]), "r"(b0), "r"(b1));
}

__device__ __forceinline__ float softplus_f(float v) {
    return fmaxf(v, 0.f) + log1pf(__expf(-fabsf(v)));
}
__device__ __forceinline__ void split_f16(float v, __half& h, __half& l) {
    h = __float2half_rn(v);
    l = __float2half_rn(v - __half2float(h));
}

// Swizzled smem byte offset inside a 128x32 fp16 tile (8KB).
__device__ __forceinline__ uint32_t tile_off(int r, int k8) {
    const int prow = r >> 1;
    const int slot = (((r & 1) << 2) | (k8 >> 3)) ^ (prow & 7);
    return (uint32_t)((prow << 7) + (slot << 4));
}

// ---------------- mma.sync GEMM ----------------------------------------------
// C[M,N] (+= over z) = A'[M,K2] @ B'^T, both K-major fp16 (2-term split layout).
// Block 128x128, K-chunk 32, 4-stage cp.async pipeline (distance 3), one
// __syncthreads per chunk, 2 CTAs/SM.
#define STAGE_B 16384
#define GSMEM (4 * STAGE_B)

template <int EPI>
__global__ __launch_bounds__(256, 2) void mma_gemm(
    const __half* __restrict__ A2, const __half* __restrict__ B2,
    float* __restrict__ C, int N, int K2, int cpz,
    const float* __restrict__ bias) {
    extern __shared__ __align__(16) char smem[];
    const uint32_t smu = smem_u32(smem);

    const int tid = threadIdx.x;
    const int lane = tid & 31;
    const int wid = tid >> 5;
    const int m0 = blockIdx.y * 128;
    const int n0 = blockIdx.x * 128;
    const int cbeg = blockIdx.z * cpz;
    float* __restrict__ Cb = C + (size_t)blockIdx.z * (size_t)MROWS * (size_t)N;

    const int wm0 = (wid & 1) * 64;
    const int wn0 = (wid >> 1) * 32;

    const int gr0 = tid >> 2, gkc = (tid & 3) * 8;
    const uint32_t d0 = tile_off(gr0, gkc);
    const uint32_t d1 = tile_off(gr0 + 64, gkc);
    const __half* Ag = A2 + (size_t)(m0 + gr0) * K2 + gkc;
    const __half* Ag2 = A2 + (size_t)(m0 + gr0 + 64) * K2 + gkc;
    const __half* Bg = B2 + (size_t)(n0 + gr0) * K2 + gkc;
    const __half* Bg2 = B2 + (size_t)(n0 + gr0 + 64) * K2 + gkc;

    auto stage_load = [&](int s, int ck) {
        const int k0 = ck * 32;
        const uint32_t sa = smu + s * STAGE_B;
        const uint32_t sb = sa + 8192;
        cp_async16(sa + d0, Ag + k0);
        cp_async16(sa + d1, Ag2 + k0);
        cp_async16(sb + d0, Bg + k0);
        cp_async16(sb + d1, Bg2 + k0);
    };

    float acc[4][4][4];
#pragma unroll
    for (int i = 0; i < 4; ++i)
#pragma unroll
        for (int j = 0; j < 4; ++j)
#pragma unroll
            for (int q = 0; q < 4; ++q) acc[i][j][q] = 0.f;

#pragma unroll
    for (int p = 0; p < 3; ++p) {
        if (p < cpz) stage_load(p, cbeg + p);
        CP_COMMIT();
    }

    const int lr = lane & 7;
    const int lb1 = (lane >> 3) & 1;
    const int lb2 = lane >> 4;
    const int ar[4] = {wm0 + 0 + lb1 * 8 + lr, wm0 + 16 + lb1 * 8 + lr,
                       wm0 + 32 + lb1 * 8 + lr, wm0 + 48 + lb1 * 8 + lr};
    const int br[2] = {wn0 + 0 + lb2 * 8 + lr, wn0 + 16 + lb2 * 8 + lr};

    for (int j = 0; j < cpz; ++j) {
        const int s = j & 3;
        CP_WAIT2();
        __syncthreads();

        if (j + 3 < cpz) stage_load((j + 3) & 3, cbeg + j + 3);
        CP_COMMIT();

        const uint32_t sa = smu + s * STAGE_B;
        const uint32_t sb = sa + 8192;
#pragma unroll
        for (int kk = 0; kk < 2; ++kk) {
            uint32_t a[4][4], b[2][4];
            const int ka = kk * 16 + lb2 * 8;
            const int kb = kk * 16 + lb1 * 8;
#pragma unroll
            for (int mt = 0; mt < 4; ++mt) ldsm_x4(a[mt], sa + tile_off(ar[mt], ka));
#pragma unroll
            for (int nt = 0; nt < 2; ++nt) ldsm_x4(b[nt], sb + tile_off(br[nt], kb));
#pragma unroll
            for (int mt = 0; mt < 4; ++mt)
#pragma unroll
                for (int nt = 0; nt < 2; ++nt)
#pragma unroll
                    for (int half = 0; half < 2; ++half)
                        mma_16816(acc[mt][nt * 2 + half], a[mt],
                                  b[nt][half * 2], b[nt][half * 2 + 1]);
        }
    }

    const int rbase = m0 + wm0 + (lane >> 2);
    const int cbase = n0 + wn0 + (lane & 3) * 2;
#pragma unroll
    for (int mt = 0; mt < 4; ++mt) {
#pragma unroll
        for (int nf = 0; nf < 4; ++nf) {
            const int row = rbase + mt * 16;
            const int col = cbase + nf * 8;
            if (col < N) {
                float v0 = acc[mt][nf][0], v1 = acc[mt][nf][1];
                float v2 = acc[mt][nf][2], v3 = acc[mt][nf][3];
                if (EPI == 1) {
                    const float b0 = bias[col], b1 = bias[col + 1];
                    v0 = softplus_f(v0 + b0); v1 = softplus_f(v1 + b1);
                    v2 = softplus_f(v2 + b0); v3 = softplus_f(v3 + b1);
                }
                *(float2*)&Cb[(size_t)row * N + col] = make_float2(v0, v1);
                *(float2*)&Cb[(size_t)(row + 8) * N + col] = make_float2(v2, v3);
            }
        }
    }
}

// ---------------- convert: W[K,N] fp32 -> B' [Npad, 2K] fp16 ----------------
__global__ __launch_bounds__(256) void convT_kernel(const float* __restrict__ W,
                                                    __half* __restrict__ out,
                                                    int K, int N) {
    __shared__ float tile[32][33];
    const int k0 = blockIdx.x * 32, n0 = blockIdx.y * 32;
    const int tx = threadIdx.x, ty = threadIdx.y;  // 32 x 8
    const int K2 = 2 * K;
#pragma unroll
    for (int r = 0; r < 32; r += 8) {
        const int n = n0 + tx;
        tile[ty + r][tx] = (n < N) ? W[(size_t)(k0 + ty + r) * N + n] : 0.f;
    }
    __syncthreads();
#pragma unroll
    for (int r = 0; r < 32; r += 8) {
        const int n = n0 + ty + r, k = k0 + tx;
        const __half h = __float2half_rn(tile[tx][ty + r]);
        __half* rowp = out + (size_t)n * K2;
        rowp[k] = h;          // pairs with A hi
        rowp[K + k] = h;      // pairs with A lo
    }
}

// ---------------- convert: A[M,K] fp32 (lda) -> A' [M,2K] fp16 --------------
__global__ __launch_bounds__(256) void convA_kernel(const float* __restrict__ A,
                                                    __half* __restrict__ out,
                                                    int K, int lda) {
    const int idx = blockIdx.x * blockDim.x + threadIdx.x;
    const int row = idx / (K / 4);
    const int c4 = (idx - row * (K / 4)) * 4;
    const int K2 = 2 * K;
    const float4 v = *reinterpret_cast<const float4*>(A + (size_t)row * lda + c4);
    __half h0, l0, h1, l1, h2, l2, h3, l3;
    split_f16(v.x, h0, l0); split_f16(v.y, h1, l1);
    split_f16(v.z, h2, l2); split_f16(v.w, h3, l3);
    __half* rowp = out + (size_t)row * K2;
    __half2* H = reinterpret_cast<__half2*>(rowp + c4);
    __half2* L = reinterpret_cast<__half2*>(rowp + K + c4);
    H[0] = __half2(h0, h1); H[1] = __half2(h2, h3);
    L[0] = __half2(l0, l1); L[1] = __half2(l2, l3);
}

// ---------------- causal depthwise conv (k=4) + SiLU -> [Ah|Al] fp16 --------
__global__ __launch_bounds__(256) void conv_silu_kernel(
    const float* __restrict__ xz, const float* __restrict__ kern,
    const float* __restrict__ kb, __half* __restrict__ xc2) {
    const int idx = blockIdx.x * blockDim.x + threadIdx.x;
    const int d4 = idx & (DI / 4 - 1);
    const int row = idx / (DI / 4);
    const int l = row & (LL - 1);
    const int d = d4 * 4;

    float4 acc = *(const float4*)(kb + d);
#pragma unroll
    for (int i = 0; i < 4; ++i) {
        const int ll = l - 3 + i;
        if (ll >= 0) {
            const float4 x4 = *(const float4*)(xz + (size_t)(row - 3 + i) * (2 * DI) + d);
            const float4 k4 = *(const float4*)(kern + i * DI + d);
            acc.x = fmaf(x4.x, k4.x, acc.x);
            acc.y = fmaf(x4.y, k4.y, acc.y);
            acc.z = fmaf(x4.z, k4.z, acc.z);
            acc.w = fmaf(x4.w, k4.w, acc.w);
        }
    }
    acc.x = acc.x * __fdividef(1.f, 1.f + __expf(-acc.x));
    acc.y = acc.y * __fdividef(1.f, 1.f + __expf(-acc.y));
    acc.z = acc.z * __fdividef(1.f, 1.f + __expf(-acc.z));
    acc.w = acc.w * __fdividef(1.f, 1.f + __expf(-acc.w));

    __half h0, l0, h1, l1, h2, l2, h3, l3;
    split_f16(acc.x, h0, l0); split_f16(acc.y, h1, l1);
    split_f16(acc.z, h2, l2); split_f16(acc.w, h3, l3);
    __half* rowp = xc2 + (size_t)row * (2 * DI);
    __half2* H = reinterpret_cast<__half2*>(rowp + d);
    __half2* L = reinterpret_cast<__half2*>(rowp + DI + d);
    H[0] = __half2(h0, h1); H[1] = __half2(h2, h3);
    L[0] = __half2(l0, l1); L[1] = __half2(l2, l3);
}

// ---------------- split-K reduce (deterministic) ----------------------------
__global__ __launch_bounds__(256) void reduce8_kernel(const float* __restrict__ part,
                                                      float* __restrict__ out) {
    const int i = blockIdx.x * blockDim.x + threadIdx.x;
    if (i < MROWS * NX) {
        float s = 0.f;
#pragma unroll
        for (int c = 0; c < 8; ++c) s += part[(size_t)c * (MROWS * NX) + i];
        out[i] = s;
    }
}

// ---------------- selective scan (u from xc2 split; y -> [Ah|Al] fp16) ------
__global__ __launch_bounds__(256) void scan_kernel(
    const __half* __restrict__ xc2, const float* __restrict__ xdbl,
    const float* __restrict__ delta, const float* __restrict__ xz,
    const float* __restrict__ A_log, const float* __restrict__ Dskip,
    __half* __restrict__ y2) {
    const int w = blockIdx.x * 8 + (threadIdx.x >> 5);
    const int lane = threadIdx.x & 31;
    const int b = w >> 10;
    const int dp = w & 1023;
    const int n = lane & 15;
    const int d = dp * 2 + (lane >> 4);

    const float An = -expf(A_log[d * DS + n]);
    const float Dv = Dskip[d];

    const size_t rb = (size_t)(b << 10);
    const float* __restrict__ dptr = delta + rb * DI + d;
    const __half* __restrict__ uh = xc2 + rb * (2 * DI) + d;
    const __half* __restrict__ ul = uh + DI;
    const float* __restrict__ zptr = xz + rb * (2 * DI) + DI + d;
    const float* __restrict__ bcb = xdbl + rb * NX;
    __half* __restrict__ yp = y2 + rb * (2 * DI) + d;

    float st = 0.f;
#pragma unroll 4
    for (int l = 0; l < LL; ++l) {
        const float dl = __ldg(dptr + (size_t)l * DI);
        const float u = __half2float(__ldg(uh + (size_t)l * (2 * DI))) +
                        __half2float(__ldg(ul + (size_t)l * (2 * DI)));
        const float Bn = __ldg(bcb + (size_t)l * NX + DR + n);
        const float Cn = __ldg(bcb + (size_t)l * NX + DR + DS + n);
        const float dA = __expf(dl * An);
        st = fmaf(dA, st, dl * u * Bn);
        float c = st * Cn;
        c += __shfl_xor_sync(0xffffffffu, c, 8);
        c += __shfl_xor_sync(0xffffffffu, c, 4);
        c += __shfl_xor_sync(0xffffffffu, c, 2);
        c += __shfl_xor_sync(0xffffffffu, c, 1);
        if (n == 0) {
            const float zv = __ldg(zptr + (size_t)l * (2 * DI));
            const float yv = fmaf(u, Dv, c) * zv * __fdividef(1.f, 1.f + __expf(-zv));
            __half h, lo2; split_f16(yv, h, lo2);
            __half* rowp = yp + (size_t)l * (2 * DI);
            rowp[0] = h;
            rowp[DI] = lo2;
        }
    }
}

// ---------------- launch ----------------------------------------------------
extern "C" void kernel_launch(void* const* d_in, const int* in_sizes, int n_in,
                              void* d_out, int out_size) {
    (void)in_sizes; (void)n_in; (void)out_size;
    const float* hidden = (const float*)d_in[0];
    const float* Win = (const float*)d_in[1];
    const float* Wx = (const float*)d_in[2];
    const float* Wdt = (const float*)d_in[3];
    const float* dt_bias = (const float*)d_in[4];
    const float* Wout = (const float*)d_in[5];
    const float* dwk = (const float*)d_in[6];
    const float* dwb = (const float*)d_in[7];
    const float* A_log = (const float*)d_in[8];
    const float* Dskip = (const float*)d_in[9];
    float* out = (float*)d_out;

    float *xz, *xdbl, *dlt, *part;
    cudaGetSymbolAddress((void**)&xz, g_xz);
    cudaGetSymbolAddress((void**)&xdbl, g_xdbl);
    cudaGetSymbolAddress((void**)&dlt, g_delta);
    cudaGetSymbolAddress((void**)&part, g_part);

    __half *WinT2, *WxT2, *WdtT2, *WoutT2, *h2, *xc2, *dt2, *y2;
    cudaGetSymbolAddress((void**)&WinT2, g_WinT2);
    cudaGetSymbolAddress((void**)&WxT2, g_WxT2);
    cudaGetSymbolAddress((void**)&WdtT2, g_WdtT2);
    cudaGetSymbolAddress((void**)&WoutT2, g_WoutT2);
    cudaGetSymbolAddress((void**)&h2, g_h2);
    cudaGetSymbolAddress((void**)&xc2, g_xc2);
    cudaGetSymbolAddress((void**)&dt2, g_dt2);
    cudaGetSymbolAddress((void**)&y2, g_y2);

    cudaFuncSetAttribute(mma_gemm<0>, cudaFuncAttributeMaxDynamicSharedMemorySize, GSMEM);
    cudaFuncSetAttribute(mma_gemm<1>, cudaFuncAttributeMaxDynamicSharedMemorySize, GSMEM);

    const dim3 tb(32, 8);

    // launches ordered so GEMM1 lands at capture index 3 (ncu profiles launch #3)
    convT_kernel<<<dim3(DM / 32, 4096 / 32), tb>>>(Win, WinT2, DM, 2 * DI);        // 0
    convA_kernel<<<(MROWS * DM / 4) / 256, 256>>>(hidden, h2, DM, DM);             // 1
    convT_kernel<<<dim3(DI / 32, 128 / 32), tb>>>(Wx, WxT2, DI, NX);               // 2

    // GEMM1: xz = hidden @ Win  (M=2048, N=4096, K'=2048)                          // 3
    mma_gemm<0><<<dim3(4096 / 128, MROWS / 128, 1), 256, GSMEM>>>(
        h2, WinT2, xz, 2 * DI, 2 * DM, 2 * DM / 32, nullptr);

    convT_kernel<<<dim3(DR / 32, DI / 32), tb>>>(Wdt, WdtT2, DR, DI);              // 4
    convT_kernel<<<dim3(DI / 32, DM / 32), tb>>>(Wout, WoutT2, DI, DM);            // 5

    // conv + silu -> xc2 [Ah|Al]                                                   // 6
    conv_silu_kernel<<<(MROWS * DI / 4) / 256, 256>>>(xz, dwk, dwb, xc2);

    // GEMM2: x_dbl = xc @ Wx  (N=96, K'=4096), split-K x8 + reduce                 // 7,8
    mma_gemm<0><<<dim3(1, MROWS / 128, 8), 256, GSMEM>>>(
        xc2, WxT2, part, NX, 2 * DI, (2 * DI / 32) / 8, nullptr);
    reduce8_kernel<<<(MROWS * NX + 255) / 256, 256>>>(part, xdbl);

    // dt slice -> A' layout (K=64, lda=96)                                         // 9
    convA_kernel<<<(MROWS * DR / 4) / 256, 256>>>(xdbl, dt2, DR, NX);

    // GEMM3: delta = softplus(dt @ Wdt + bias)  (N=2048, K'=128)                   // 10
    mma_gemm<1><<<dim3(DI / 128, MROWS / 128, 1), 256, GSMEM>>>(
        dt2, WdtT2, dlt, DI, 2 * DR, 2 * DR / 32, dt_bias);

    // selective scan -> y2 [Ah|Al]                                                 // 11
    scan_kernel<<<256, 256>>>(xc2, xdbl, dlt, xz, A_log, Dskip, y2);

    // GEMM4: out = y @ Wout  (N=1024, K'=4096)                                     // 12
    mma_gemm<0><<<dim3(DM / 128, MROWS / 128, 1), 256, GSMEM>>>(
        y2, WoutT2, out, DM, 2 * DI, 2 * DI / 32, nullptr);
}